// round 14
// baseline (speedup 1.0000x reference)
#include <cuda_runtime.h>
#include <cuda_bf16.h>
#include <cmath>
#include <cstdint>

// ============================================================================
// Problem constants
// ============================================================================
#define NPTS   32768
#define NDATA  1024
#define NQUAD  1000
#define TOTALP (NPTS + NDATA + NQUAD + 2)     // 34794
#define PTILE  25
#define NTILES ((TOTALP + PTILE - 1) / PTILE) // 1392
#define THREADS 512

static constexpr double kEI = 5.0e7 * (((0.02 * 0.02 * 0.02) * 0.02) / 12.0);
static constexpr double kWC = 1.0 / kEI;

// ============================================================================
// Device globals (scratch)
// ============================================================================
__device__ float g_tn[NQUAD];
__device__ float g_wsum;
__device__ float g_fsq[NQUAD];
__device__ float g_pred[NDATA];
__device__ float g_bdry[10];
__device__ unsigned int g_done = 0;

// ============================================================================
// Host-side Gauss-Legendre tables (static init)
// ============================================================================
struct GLTables {
    float tn[NQUAD];
    float wsum;
    GLTables() {
        const int n = NQUAD;
        const double pi = 3.14159265358979323846;
        double sumw = 0.0;
        for (int k = 0; k < n; k++) {
            double x = cos(pi * (k + 0.75) / (n + 0.5));
            for (int it = 0; it < 100; it++) {
                double p0 = 1.0, p1 = x;
                for (int m = 2; m <= n; m++) {
                    double p2 = ((2.0 * m - 1.0) * x * p1 - (m - 1.0) * p0) / m;
                    p0 = p1; p1 = p2;
                }
                double dp = n * (x * p1 - p0) / (x * x - 1.0);
                double dx = p1 / dp;
                x -= dx;
                if (fabs(dx) < 1e-15) break;
            }
            double p0 = 1.0, p1 = x;
            for (int m = 2; m <= n; m++) {
                double p2 = ((2.0 * m - 1.0) * x * p1 - (m - 1.0) * p0) / m;
                p0 = p1; p1 = p2;
            }
            double dp = n * (x * p1 - p0) / (x * x - 1.0);
            double w = 2.0 / ((1.0 - x * x) * dp * dp);
            sumw += (double)(float)w;
            tn[k] = (float)(0.5 * x + 0.5);
        }
        wsum = (float)sumw;
    }
};
static GLTables g_gl;

// ============================================================================
// Shared memory layout. bf16 operand matrices UNPADDED (256 B/row) with a
// 16B-chunk XOR swizzle: off(row,cb) = row*256 + (cb ^ ((row&7)<<4)).
// Two f32 staging buffers (stride 34), one per 256-thread team.
// NO static __shared__ anywhere — dynamic smem is at the 227 KB cap.
// ============================================================================
static constexpr int SM_B1H  = 0;         // 32768 each
static constexpr int SM_B1L  = 32768;
static constexpr int SM_B2H  = 65536;
static constexpr int SM_B2L  = 98304;
static constexpr int SM_A0   = 131072;
static constexpr int SM_A1   = 163840;
static constexpr int SM_DSTA = 196608;    // [128][34] f32 = 17408
static constexpr int SM_DSTB = 214016;    // 17408
static constexpr int SM_SB1  = 231424;    // 512 (also is_last slot in finalize)
static constexpr int SM_SB2  = 231936;    // 512
static constexpr int SMEM_BYTES = 232448; // == 227 KB cap, all dynamic

static constexpr int DSTRIDE = 34;
static constexpr int HSTRIDE = 17;

__device__ __forceinline__ uint32_t swz_off(int row, int cb) {
    return (uint32_t)(row * 256 + (cb ^ ((row & 7) << 4)));
}

// ============================================================================
// PTX helpers
// ============================================================================
#define LDSM_X4(r0, r1, r2, r3, addr) \
    asm volatile("ldmatrix.sync.aligned.m8n8.x4.shared.b16 {%0,%1,%2,%3},[%4];" \
                 : "=r"(r0), "=r"(r1), "=r"(r2), "=r"(r3) : "r"(addr))
#define MMA_BF16(d, a0, a1, a2, a3, b0, b1) \
    asm volatile("mma.sync.aligned.m16n8k16.row.col.f32.bf16.bf16.f32 " \
                 "{%0,%1,%2,%3},{%4,%5,%6,%7},{%8,%9},{%0,%1,%2,%3};" \
                 : "+f"((d)[0]), "+f"((d)[1]), "+f"((d)[2]), "+f"((d)[3]) \
                 : "r"(a0), "r"(a1), "r"(a2), "r"(a3), "r"(b0), "r"(b1))
#define NBAR(id) asm volatile("bar.sync %0, 256;" :: "r"(id) : "memory")

// ============================================================================
// Fast branchless tanh: tanh(a) = 1 - 2/(e^{2a}+1), one Newton step on rcp.
// ============================================================================
__device__ __forceinline__ float fast_tanh(float a)
{
    float ac = fminf(fmaxf(a, -15.0f), 15.0f);
    float f;
    asm("ex2.approx.f32 %0, %1;" : "=f"(f) : "f"(ac * 2.8853900817779268f));
    float d = f + 1.0f;
    float r;
    asm("rcp.approx.f32 %0, %1;" : "=f"(r) : "f"(d));
    r = r * (2.0f - d * r);
    return 1.0f - 2.0f * r;
}

// ============================================================================
// tanh jet (Faa di Bruno)
// ============================================================================
__device__ __forceinline__ void tanh_jet(float a0, float a1, float a2, float a3, float a4,
                                         float& y0, float& y1, float& y2, float& y3, float& y4)
{
    float t  = fast_tanh(a0);
    float t2 = t * t;
    float g1 = 1.0f - t2;
    float u2 = -2.0f * t * g1;
    float u3 = g1 * (6.0f * t2 - 2.0f);
    float u4 = g1 * (16.0f * t - 24.0f * t2 * t);
    float a1s = a1 * a1;
    y0 = t;
    y1 = g1 * a1;
    y2 = u2 * a1s + g1 * a2;
    y3 = u3 * a1s * a1 + 3.0f * u2 * a1 * a2 + g1 * a3;
    y4 = u4 * a1s * a1s + 6.0f * u3 * a1s * a2
       + u2 * (3.0f * a2 * a2 + 4.0f * a1 * a3) + g1 * a4;
}

// split two adjacent f32 -> paired bf16 hi/lo, one 4B store each (swizzled)
__device__ __forceinline__ void split_store_pair(char* A0, char* A1, int row, int k0,
                                                 float v0, float v1)
{
    __nv_bfloat16 h0 = __float2bfloat16(v0);
    __nv_bfloat16 h1 = __float2bfloat16(v1);
    float l0 = v0 - __bfloat162float(h0);
    float l1 = v1 - __bfloat162float(h1);
    uint32_t off = swz_off(row, 2 * k0);
    __nv_bfloat162 hpv; hpv.x = h0; hpv.y = h1;
    __nv_bfloat162 lpv; lpv.x = __float2bfloat16(l0); lpv.y = __float2bfloat16(l1);
    *(__nv_bfloat162*)(A0 + off) = hpv;
    *(__nv_bfloat162*)(A1 + off) = lpv;
}

// ============================================================================
// Warp GEMM: m32 x n32 per warp (4m x 4n grid of 16 warps), swizzled operands.
// Per kt: 4 A-LDSM + 4 B-LDSM (vs 2+8 for m16n64) — B fragments reused by
// both m-subtiles.  D = Ahi*Bhi + Ahi*Blo + Alo*Bhi (bf16 split, f32 acc).
// ============================================================================
__device__ __forceinline__ void warp_gemm(
    uint32_t aAhi, uint32_t aAlo, uint32_t aBh, uint32_t aBl,
    uint32_t baseArow, uint32_t baseBrow, uint32_t cb0A, uint32_t cb0B,
    uint32_t sx, float (&D)[2][4][4])
{
#pragma unroll
    for (int kt = 0; kt < 8; kt++) {
        uint32_t offA = (uint32_t)((cb0A + kt * 32) ^ sx);
        uint32_t offB = (uint32_t)((cb0B + kt * 32) ^ sx);
        uint32_t ah[2][4], al[2][4];
        LDSM_X4(ah[0][0], ah[0][1], ah[0][2], ah[0][3], aAhi + baseArow + offA);
        LDSM_X4(ah[1][0], ah[1][1], ah[1][2], ah[1][3], aAhi + baseArow + 4096 + offA);
        LDSM_X4(al[0][0], al[0][1], al[0][2], al[0][3], aAlo + baseArow + offA);
        LDSM_X4(al[1][0], al[1][1], al[1][2], al[1][3], aAlo + baseArow + 4096 + offA);
#pragma unroll
        for (int p = 0; p < 2; p++) {
            uint32_t rb = baseBrow + (uint32_t)(p * 4096);
            uint32_t bh0, bh1, bh2, bh3, bl0, bl1, bl2, bl3;
            LDSM_X4(bh0, bh1, bh2, bh3, aBh + rb + offB);
            LDSM_X4(bl0, bl1, bl2, bl3, aBl + rb + offB);
#pragma unroll
            for (int ms = 0; ms < 2; ms++) {
                MMA_BF16(D[ms][2*p],   ah[ms][0], ah[ms][1], ah[ms][2], ah[ms][3], bh0, bh1);
                MMA_BF16(D[ms][2*p],   ah[ms][0], ah[ms][1], ah[ms][2], ah[ms][3], bl0, bl1);
                MMA_BF16(D[ms][2*p],   al[ms][0], al[ms][1], al[ms][2], al[ms][3], bh0, bh1);
                MMA_BF16(D[ms][2*p+1], ah[ms][0], ah[ms][1], ah[ms][2], ah[ms][3], bh2, bh3);
                MMA_BF16(D[ms][2*p+1], ah[ms][0], ah[ms][1], ah[ms][2], ah[ms][3], bl2, bl3);
                MMA_BF16(D[ms][2*p+1], al[ms][0], al[ms][1], al[ms][2], al[ms][3], bh2, bh3);
            }
        }
    }
}

// stage this warp's 32x32 fragments (its n-chunk) into the team Dst buffer
__device__ __forceinline__ void stage_frags(float* DstT, const float (&D)[2][4][4],
                                            int wm, int lane)
{
    int cb = 2 * (lane & 3);
#pragma unroll
    for (int ms = 0; ms < 2; ms++) {
        int r0 = 32 * wm + 16 * ms + (lane >> 2);
#pragma unroll
        for (int nt = 0; nt < 4; nt++) {
            int col = nt * 8 + cb;
            *(float2*)&DstT[r0 * DSTRIDE + col]       = make_float2(D[ms][nt][0], D[ms][nt][1]);
            *(float2*)&DstT[(r0 + 8) * DSTRIDE + col] = make_float2(D[ms][nt][2], D[ms][nt][3]);
        }
    }
}

// write one (point, comp) result
__device__ __forceinline__ void write_point(float* out, int p, int c, float v,
                                            float CW, float CM)
{
    if (p < NPTS) {
        float sc = (c == 2 || c == 3) ? CM : CW;
        out[c * NPTS + p] = sc * v;
    } else if (p < NPTS + NDATA) {
        if (c == 0) g_pred[p - NPTS] = v;
    } else if (p < NPTS + NDATA + NQUAD) {
        if (c == 2) g_fsq[p - NPTS - NDATA] = v * v;
    } else if (p == NPTS + NDATA + NQUAD) {
        g_bdry[c] = v;
    } else {
        g_bdry[5 + c] = v;
    }
}

// ============================================================================
// Main kernel: persistent, 512 threads = 16 GEMM warps (4m x 4n, m32n32).
// Epilogues: TWO independent 256-thread teams (named barriers), one per
// n-half; block barrier between L1 GEMM (reads all A) and the epilogue that
// overwrites A.  Fused finalize in last block.
// ============================================================================
__global__ void __launch_bounds__(THREADS, 1)
pinn_mma(const float* __restrict__ W0, const float* __restrict__ b0,
         const float* __restrict__ W1, const float* __restrict__ b1,
         const float* __restrict__ W2, const float* __restrict__ b2,
         const float* __restrict__ W3, const float* __restrict__ b3,
         const float* __restrict__ x,  const float* __restrict__ data_x,
         const float* __restrict__ data_w,
         float* __restrict__ out)
{
    extern __shared__ char sm[];
    char*  A0p  = sm + SM_A0;
    char*  A1p  = sm + SM_A1;
    float* DstA = (float*)(sm + SM_DSTA);
    float* DstB = (float*)(sm + SM_DSTB);
    float* sb1  = (float*)(sm + SM_SB1);
    float* sb2  = (float*)(sm + SM_SB2);

    const int tid     = threadIdx.x;
    const int warp    = tid >> 5;
    const int lane    = tid & 31;
    const int wm      = warp & 3;        // m-tile 0..3 (32 rows each)
    const int wn      = warp >> 2;       // n-chunk 0..3 (32 cols each)
    const int team    = warp >> 3;       // 0: chunks 0,1  1: chunks 2,3
    const int teamtid = tid & 255;
    const int barid   = 1 + team;
    float* DstT = team ? DstB : DstA;

    const uint32_t smw  = (uint32_t)__cvta_generic_to_shared(sm);
    const uint32_t aA0  = smw + SM_A0;
    const uint32_t aA1  = smw + SM_A1;
    const uint32_t aB1H = smw + SM_B1H;
    const uint32_t aB1L = smw + SM_B1L;
    const uint32_t aB2H = smw + SM_B2H;
    const uint32_t aB2L = smw + SM_B2L;

    // ---- build weight splits: Wst[n][k] = W[k][n], hi/lo bf16, swizzled ----
    for (int idx = tid; idx < 16384; idx += THREADS) {
        int k = idx >> 7, n = idx & 127;
        uint32_t off = swz_off(n, 2 * k);
        float v1 = W1[idx];
        float v2 = W2[idx];
        __nv_bfloat16 h1 = __float2bfloat16(v1);
        __nv_bfloat16 h2 = __float2bfloat16(v2);
        *(__nv_bfloat16*)(sm + SM_B1H + off) = h1;
        *(__nv_bfloat16*)(sm + SM_B1L + off) = __float2bfloat16(v1 - __bfloat162float(h1));
        *(__nv_bfloat16*)(sm + SM_B2H + off) = h2;
        *(__nv_bfloat16*)(sm + SM_B2L + off) = __float2bfloat16(v2 - __bfloat162float(h2));
    }
    if (tid < 128) { sb1[tid] = b1[tid]; sb2[tid] = b2[tid]; }
    __syncthreads();

    // ldmatrix lane address components (swizzled layout)
    const uint32_t sx       = (uint32_t)((lane & 7) << 4);
    const uint32_t baseArow = (uint32_t)((32 * wm + (lane & 15)) * 256);
    const uint32_t cb0A     = (uint32_t)((lane >> 4) * 16);
    const uint32_t baseBrow = (uint32_t)((32 * wn + ((lane >> 4) << 3) + (lane & 7)) * 256);
    const uint32_t cb0B     = (uint32_t)(((lane >> 3) & 1) * 16);

    const float CW  = (float)(kWC);
    const float CM  = (float)(-kEI * kWC);
    const float b3v = __ldg(&b3[0]);

    for (int tile = blockIdx.x; tile < NTILES; tile += gridDim.x) {
        const int base = tile * PTILE;
        const int npt  = min(PTILE, TOTALP - base);
        const int NP2  = npt * 16;

        // ---- layer 0: build A splits directly from global coords ----
#pragma unroll
        for (int e = 0; e < 4; e++) {
            int idx = tid + e * THREADS;
            if (idx < npt * 64) {
                int pt = idx >> 6, up = idx & 63;
                int u0 = 2 * up;
                int p = base + pt;
                float s;
                if (p < NPTS)                       s = __ldg(&x[p]);
                else if (p < NPTS + NDATA)          s = __ldg(&data_x[p - NPTS]);
                else if (p < NPTS + NDATA + NQUAD)  s = g_tn[p - NPTS - NDATA];
                else                                s = (p == NPTS + NDATA + NQUAD) ? 0.0f : 1.0f;
                float wa = __ldg(&W0[u0]),     ba = __ldg(&b0[u0]);
                float wb = __ldg(&W0[u0 + 1]), bb = __ldg(&b0[u0 + 1]);
                float ya[5], yb[5];
                tanh_jet(fmaf(wa, s, ba), wa, 0.f, 0.f, 0.f,
                         ya[0], ya[1], ya[2], ya[3], ya[4]);
                tanh_jet(fmaf(wb, s, bb), wb, 0.f, 0.f, 0.f,
                         yb[0], yb[1], yb[2], yb[3], yb[4]);
                int r0 = 5 * pt;
#pragma unroll
                for (int c = 0; c < 5; c++)
                    split_store_pair(A0p, A1p, r0 + c, u0, ya[c], yb[c]);
            }
        }
        __syncthreads();

        // ================= LAYER 1 GEMM =================
        float D[2][4][4];
#pragma unroll
        for (int ms = 0; ms < 2; ms++)
#pragma unroll
            for (int nt = 0; nt < 4; nt++)
                { D[ms][nt][0]=D[ms][nt][1]=D[ms][nt][2]=D[ms][nt][3]=0.f; }
        warp_gemm(aA0, aA1, aB1H, aB1L, baseArow, baseBrow, cb0A, cb0B, sx, D);

        // Block-wide barrier: every warp reads ALL of A in the GEMM above;
        // the epilogue below overwrites A.
        __syncthreads();

        // ---- layer 1 epilogue: 2 chunks per team, named barriers ----
        for (int lc = 0; lc < 2; lc++) {
            if ((wn & 1) == lc) stage_frags(DstT, D, wm, lane);
            NBAR(barid);
#pragma unroll
            for (int e = 0; e < 2; e++) {
                int idx = teamtid + e * 256;
                if (idx < NP2) {
                    int pt = idx >> 4, up = idx & 15;
                    int u0 = (2 * team + lc) * 32 + 2 * up;
                    float z0[5], z1[5];
#pragma unroll
                    for (int c = 0; c < 5; c++) {
                        float2 zz = *(float2*)&DstT[(5 * pt + c) * DSTRIDE + 2 * up];
                        z0[c] = zz.x; z1[c] = zz.y;
                    }
                    z0[0] += sb1[u0]; z1[0] += sb1[u0 + 1];
                    float ya[5], yb[5];
                    tanh_jet(z0[0], z0[1], z0[2], z0[3], z0[4], ya[0], ya[1], ya[2], ya[3], ya[4]);
                    tanh_jet(z1[0], z1[1], z1[2], z1[3], z1[4], yb[0], yb[1], yb[2], yb[3], yb[4]);
                    int r0 = 5 * pt;
#pragma unroll
                    for (int c = 0; c < 5; c++)
                        split_store_pair(A0p, A1p, r0 + c, u0, ya[c], yb[c]);
                }
            }
            NBAR(barid);
        }
        __syncthreads();   // both teams' A writes visible before layer-2 GEMM

        // ================= LAYER 2 GEMM =================
#pragma unroll
        for (int ms = 0; ms < 2; ms++)
#pragma unroll
            for (int nt = 0; nt < 4; nt++)
                { D[ms][nt][0]=D[ms][nt][1]=D[ms][nt][2]=D[ms][nt][3]=0.f; }
        warp_gemm(aA0, aA1, aB2H, aB2L, baseArow, baseBrow, cb0A, cb0B, sx, D);
        // (no A writes below until next tile's layer 0; Dst buffers are
        //  team-private, so no block barrier needed here.)

        // ---- layer 2 epilogue + head partials (teams) ----
        float hp[2][5];
#pragma unroll
        for (int e = 0; e < 2; e++)
#pragma unroll
            for (int c = 0; c < 5; c++) hp[e][c] = 0.0f;

        for (int lc = 0; lc < 2; lc++) {
            if ((wn & 1) == lc) stage_frags(DstT, D, wm, lane);
            NBAR(barid);
#pragma unroll
            for (int e = 0; e < 2; e++) {
                int idx = teamtid + e * 256;
                if (idx < NP2) {
                    int pt = idx >> 4, up = idx & 15;
                    int u0 = (2 * team + lc) * 32 + 2 * up;
                    float z0[5], z1[5];
#pragma unroll
                    for (int c = 0; c < 5; c++) {
                        float2 zz = *(float2*)&DstT[(5 * pt + c) * DSTRIDE + 2 * up];
                        z0[c] = zz.x; z1[c] = zz.y;
                    }
                    z0[0] += sb2[u0]; z1[0] += sb2[u0 + 1];
                    float ya[5], yb[5];
                    tanh_jet(z0[0], z0[1], z0[2], z0[3], z0[4], ya[0], ya[1], ya[2], ya[3], ya[4]);
                    tanh_jet(z1[0], z1[1], z1[2], z1[3], z1[4], yb[0], yb[1], yb[2], yb[3], yb[4]);
                    float wa = __ldg(&W3[u0]), wb = __ldg(&W3[u0 + 1]);
#pragma unroll
                    for (int c = 0; c < 5; c++)
                        hp[e][c] = fmaf(wa, ya[c], fmaf(wb, yb[c], hp[e][c]));
                }
            }
            NBAR(barid);
        }

        // ---- head partials -> team buffer (stride 17) ----
#pragma unroll
        for (int e = 0; e < 2; e++) {
            int idx = teamtid + e * 256;
            if (idx < NP2) {
                int pt = idx >> 4, up = idx & 15;
#pragma unroll
                for (int c = 0; c < 5; c++)
                    DstT[(pt * 5 + c) * HSTRIDE + up] = hp[e][c];
            }
        }
        __syncthreads();

        // ---- fixed-order reduce over both teams' partials ----
        if (tid < npt * 5) {
            int pt = tid / 5, c = tid % 5;
            float v = 0.0f;
            const float* sa = DstA + tid * HSTRIDE;
            const float* sb = DstB + tid * HSTRIDE;
#pragma unroll
            for (int up = 0; up < 16; up++) v += sa[up];
#pragma unroll
            for (int up = 0; up < 16; up++) v += sb[up];
            if (c == 0) v += b3v;
            write_point(out, base + pt, c, v, CW, CM);
        }
        // next tile's layer0 writes only A; its post-layer0 __syncthreads
        // orders everything before the GEMM.
    }

    // ======================= fused finalize (last block) =======================
    __threadfence();
    __syncthreads();
    volatile int* is_last = (volatile int*)(sm + SM_SB1);   // sb1 dead after loop
    if (tid == 0) {
        unsigned int v = atomicAdd(&g_done, 1u);
        *is_last = (v == (unsigned)(gridDim.x - 1)) ? 1 : 0;
    }
    __syncthreads();
    if (*is_last) {
        __threadfence();
        double* sd = (double*)(sm);

        double acc = 0.0;
        for (int i = tid; i < NQUAD; i += THREADS) acc += (double)g_fsq[i];
        sd[tid] = acc;
        __syncthreads();
        for (int off = THREADS / 2; off > 0; off >>= 1) {
            if (tid < off) sd[tid] += sd[tid + off];
            __syncthreads();
        }
        double S_fsq = sd[0];
        __syncthreads();

        const float wcf = (float)kWC;
        double accd = 0.0;
        for (int i = tid; i < NDATA; i += THREADS) {
            float r = g_pred[i] - data_w[i] / wcf;
            accd += (double)(r * r);
        }
        sd[tid] = accd;
        __syncthreads();
        for (int off = THREADS / 2; off > 0; off >>= 1) {
            if (tid < off) sd[tid] += sd[tid + off];
            __syncthreads();
        }
        double S_data = sd[0];

        if (tid == 0) {
            float quad   = g_wsum * (float)S_fsq;
            float inter  = (float)(0.5 * kEI * (kWC * kWC) * 0.5) * quad;
            float wL     = g_bdry[5];
            float exter  = (float)(5.0 * kWC) * wL;
            float res_pel = inter - exter;

            float w0v = g_bdry[0], dw0 = g_bdry[1];
            float res_dir = (w0v * w0v + dw0 * dw0) * 0.5f;

            float ddwL = g_bdry[7], dddwL = g_bdry[8];
            float Fb   = (float)(-kEI * kWC) * dddwL;
            float tnn  = Fb / 5.0f - 1.0f;
            float res_neu = (tnn * tnn + ddwL * ddwL) * 0.5f;

            float res_data = (float)(S_data / (double)NDATA);

            out[5 * NPTS] = res_pel + (res_dir + res_neu) * 0.5f + res_data;
            g_done = 0;   // reset for next graph replay
        }
    }
}

// ============================================================================
// kernel_launch
// ============================================================================
extern "C" void kernel_launch(void* const* d_in, const int* in_sizes, int n_in,
                              void* d_out, int out_size)
{
    (void)n_in; (void)out_size;
    const float *W0, *b0, *W1, *b1, *W2, *b2, *W3, *b3, *x, *dxp, *dwp;
    if (in_sizes[0] == NPTS) {
        x   = (const float*)d_in[0];
        dxp = (const float*)d_in[1];
        dwp = (const float*)d_in[2];
        W0  = (const float*)d_in[3];  b0 = (const float*)d_in[4];
        W1  = (const float*)d_in[5];  b1 = (const float*)d_in[6];
        W2  = (const float*)d_in[7];  b2 = (const float*)d_in[8];
        W3  = (const float*)d_in[9];  b3 = (const float*)d_in[10];
    } else {
        W0  = (const float*)d_in[0];  b0 = (const float*)d_in[1];
        W1  = (const float*)d_in[2];  b1 = (const float*)d_in[3];
        W2  = (const float*)d_in[4];  b2 = (const float*)d_in[5];
        W3  = (const float*)d_in[6];  b3 = (const float*)d_in[7];
        x   = (const float*)d_in[8];
        dxp = (const float*)d_in[9];
        dwp = (const float*)d_in[10];
    }

    cudaMemcpyToSymbolAsync(g_tn,   g_gl.tn,    sizeof(float) * NQUAD, 0,
                            cudaMemcpyHostToDevice, 0);
    cudaMemcpyToSymbolAsync(g_wsum, &g_gl.wsum, sizeof(float), 0,
                            cudaMemcpyHostToDevice, 0);

    int sms = 148;
    cudaDeviceGetAttribute(&sms, cudaDevAttrMultiProcessorCount, 0);

    cudaFuncSetAttribute(pinn_mma, cudaFuncAttributeMaxDynamicSharedMemorySize,
                         SMEM_BYTES);

    pinn_mma<<<sms, THREADS, SMEM_BYTES>>>(W0, b0, W1, b1, W2, b2, W3, b3,
                                           x, dxp, dwp, (float*)d_out);
}

// round 16
// speedup vs baseline: 1.2132x; 1.2132x over previous
#include <cuda_runtime.h>
#include <cuda_fp16.h>
#include <cmath>
#include <cstdint>

// ============================================================================
// Problem constants
// ============================================================================
#define NPTS   32768
#define NDATA  1024
#define NQUAD  1000
#define TOTALP (NPTS + NDATA + NQUAD + 2)     // 34794
#define PTILE  25
#define NTILES ((TOTALP + PTILE - 1) / PTILE) // 1392
#define THREADS 512

static constexpr double kEI = 5.0e7 * (((0.02 * 0.02 * 0.02) * 0.02) / 12.0);
static constexpr double kWC = 1.0 / kEI;

// ============================================================================
// Device globals (scratch)
// ============================================================================
__device__ float g_tn[NQUAD];
__device__ float g_wsum;
__device__ float g_fsq[NQUAD];
__device__ float g_pred[NDATA];
__device__ float g_bdry[10];
__device__ unsigned int g_done = 0;

// ============================================================================
// Host-side Gauss-Legendre tables (static init)
// ============================================================================
struct GLTables {
    float tn[NQUAD];
    float wsum;
    GLTables() {
        const int n = NQUAD;
        const double pi = 3.14159265358979323846;
        double sumw = 0.0;
        for (int k = 0; k < n; k++) {
            double x = cos(pi * (k + 0.75) / (n + 0.5));
            for (int it = 0; it < 100; it++) {
                double p0 = 1.0, p1 = x;
                for (int m = 2; m <= n; m++) {
                    double p2 = ((2.0 * m - 1.0) * x * p1 - (m - 1.0) * p0) / m;
                    p0 = p1; p1 = p2;
                }
                double dp = n * (x * p1 - p0) / (x * x - 1.0);
                double dx = p1 / dp;
                x -= dx;
                if (fabs(dx) < 1e-15) break;
            }
            double p0 = 1.0, p1 = x;
            for (int m = 2; m <= n; m++) {
                double p2 = ((2.0 * m - 1.0) * x * p1 - (m - 1.0) * p0) / m;
                p0 = p1; p1 = p2;
            }
            double dp = n * (x * p1 - p0) / (x * x - 1.0);
            double w = 2.0 / ((1.0 - x * x) * dp * dp);
            sumw += (double)(float)w;
            tn[k] = (float)(0.5 * x + 0.5);
        }
        wsum = (float)sumw;
    }
};
static GLTables g_gl;

// ============================================================================
// Shared memory layout. fp16 operand matrices UNPADDED (256 B/row) with a
// 16B-chunk XOR swizzle: off(row,cb) = row*256 + (cb ^ ((row&7)<<4)).
// Activations: single fp16 buffer.  Weights: fp16 hi/lo split (22-bit eff).
// Two f32 staging buffers (stride 34), one per 256-thread team.
// ============================================================================
static constexpr int SM_B1H  = 0;         // 32768 each
static constexpr int SM_B1L  = 32768;
static constexpr int SM_B2H  = 65536;
static constexpr int SM_B2L  = 98304;
static constexpr int SM_A0   = 131072;    // activations (fp16)
static constexpr int SM_DSTA = 163840;    // [128][34] f32 = 17408
static constexpr int SM_DSTB = 181248;    // 17408
static constexpr int SM_SB1  = 198656;    // 512 (also is_last slot in finalize)
static constexpr int SM_SB2  = 199168;    // 512
static constexpr int SMEM_BYTES = 199680;

static constexpr int DSTRIDE = 34;
static constexpr int HSTRIDE = 17;

__device__ __forceinline__ uint32_t swz_off(int row, int cb) {
    return (uint32_t)(row * 256 + (cb ^ ((row & 7) << 4)));
}

// ============================================================================
// PTX helpers
// ============================================================================
#define LDSM_X4(r0, r1, r2, r3, addr) \
    asm volatile("ldmatrix.sync.aligned.m8n8.x4.shared.b16 {%0,%1,%2,%3},[%4];" \
                 : "=r"(r0), "=r"(r1), "=r"(r2), "=r"(r3) : "r"(addr))
#define MMA_F16(d, a0, a1, a2, a3, b0, b1) \
    asm volatile("mma.sync.aligned.m16n8k16.row.col.f32.f16.f16.f32 " \
                 "{%0,%1,%2,%3},{%4,%5,%6,%7},{%8,%9},{%0,%1,%2,%3};" \
                 : "+f"((d)[0]), "+f"((d)[1]), "+f"((d)[2]), "+f"((d)[3]) \
                 : "r"(a0), "r"(a1), "r"(a2), "r"(a3), "r"(b0), "r"(b1))
#define NBAR(id) asm volatile("bar.sync %0, 256;" :: "r"(id) : "memory")

// ============================================================================
// Fast branchless tanh: tanh(a) = 1 - 2/(e^{2a}+1), one Newton step on rcp.
// ============================================================================
__device__ __forceinline__ float fast_tanh(float a)
{
    float ac = fminf(fmaxf(a, -15.0f), 15.0f);
    float f;
    asm("ex2.approx.f32 %0, %1;" : "=f"(f) : "f"(ac * 2.8853900817779268f));
    float d = f + 1.0f;
    float r;
    asm("rcp.approx.f32 %0, %1;" : "=f"(r) : "f"(d));
    r = r * (2.0f - d * r);
    return 1.0f - 2.0f * r;
}

// ============================================================================
// tanh jet (Faa di Bruno)
// ============================================================================
__device__ __forceinline__ void tanh_jet(float a0, float a1, float a2, float a3, float a4,
                                         float& y0, float& y1, float& y2, float& y3, float& y4)
{
    float t  = fast_tanh(a0);
    float t2 = t * t;
    float g1 = 1.0f - t2;
    float u2 = -2.0f * t * g1;
    float u3 = g1 * (6.0f * t2 - 2.0f);
    float u4 = g1 * (16.0f * t - 24.0f * t2 * t);
    float a1s = a1 * a1;
    y0 = t;
    y1 = g1 * a1;
    y2 = u2 * a1s + g1 * a2;
    y3 = u3 * a1s * a1 + 3.0f * u2 * a1 * a2 + g1 * a3;
    y4 = u4 * a1s * a1s + 6.0f * u3 * a1s * a2
       + u2 * (3.0f * a2 * a2 + 4.0f * a1 * a3) + g1 * a4;
}

// store two adjacent f32 as paired fp16, one 4B store (swizzled)
__device__ __forceinline__ void store_pair_h(char* A0, int row, int k0,
                                             float v0, float v1)
{
    __half2 hpv;
    hpv.x = __float2half(v0);
    hpv.y = __float2half(v1);
    *(__half2*)(A0 + swz_off(row, 2 * k0)) = hpv;
}

// ============================================================================
// Warp GEMM: m16 x n64 per warp (8m x 2n grid), swizzled operands.
// 2-pass split: D = A*Whi + A*Wlo  (weights 22-bit effective via fp16 hi/lo;
// activations fp16-rounded, RN err 2^-12).  Per kt: 1 A-LDSM + 8 B-LDSM.
// ============================================================================
__device__ __forceinline__ void warp_gemm(
    uint32_t aA, uint32_t aBh, uint32_t aBl,
    uint32_t baseArow, uint32_t baseBrow, uint32_t cb0A, uint32_t cb0B,
    uint32_t sx, float (&D)[8][4])
{
#pragma unroll
    for (int kt = 0; kt < 8; kt++) {
        uint32_t offA = (uint32_t)((cb0A + kt * 32) ^ sx);
        uint32_t offB = (uint32_t)((cb0B + kt * 32) ^ sx);
        uint32_t a0, a1, a2, a3;
        LDSM_X4(a0, a1, a2, a3, aA + baseArow + offA);
#pragma unroll
        for (int p = 0; p < 4; p++) {
            uint32_t rb = baseBrow + (uint32_t)(p * 4096);
            uint32_t bh0, bh1, bh2, bh3, bl0, bl1, bl2, bl3;
            LDSM_X4(bh0, bh1, bh2, bh3, aBh + rb + offB);
            LDSM_X4(bl0, bl1, bl2, bl3, aBl + rb + offB);
            MMA_F16(D[2*p],   a0, a1, a2, a3, bh0, bh1);
            MMA_F16(D[2*p],   a0, a1, a2, a3, bl0, bl1);
            MMA_F16(D[2*p+1], a0, a1, a2, a3, bh2, bh3);
            MMA_F16(D[2*p+1], a0, a1, a2, a3, bl2, bl3);
        }
    }
}

// stage this warp's fragments for local chunk lc (cols 32*lc.. of its n-half)
__device__ __forceinline__ void stage_frags(float* DstT, const float (&D)[8][4],
                                            int wm, int lane, int lc)
{
    int r0 = 16 * wm + (lane >> 2);
    int cb = (lane & 3) * 2;
#pragma unroll
    for (int q = 0; q < 4; q++) {
        int nt = lc * 4 + q;
        *(float2*)&DstT[r0 * DSTRIDE + q * 8 + cb] = make_float2(D[nt][0], D[nt][1]);
        *(float2*)&DstT[(r0 + 8) * DSTRIDE + q * 8 + cb] = make_float2(D[nt][2], D[nt][3]);
    }
}

// write one (point, comp) result
__device__ __forceinline__ void write_point(float* out, int p, int c, float v,
                                            float CW, float CM)
{
    if (p < NPTS) {
        float sc = (c == 2 || c == 3) ? CM : CW;
        out[c * NPTS + p] = sc * v;
    } else if (p < NPTS + NDATA) {
        if (c == 0) g_pred[p - NPTS] = v;
    } else if (p < NPTS + NDATA + NQUAD) {
        if (c == 2) g_fsq[p - NPTS - NDATA] = v * v;
    } else if (p == NPTS + NDATA + NQUAD) {
        g_bdry[c] = v;
    } else {
        g_bdry[5 + c] = v;
    }
}

// ============================================================================
// Main kernel: persistent, 512 threads = 16 GEMM warps (8m x 2n).
// Epilogues: TWO independent 256-thread teams (named barriers); block barrier
// between L1 GEMM (reads all A) and the epilogue that overwrites A.
// Fused finalize in last block.
// ============================================================================
__global__ void __launch_bounds__(THREADS, 1)
pinn_mma(const float* __restrict__ W0, const float* __restrict__ b0,
         const float* __restrict__ W1, const float* __restrict__ b1,
         const float* __restrict__ W2, const float* __restrict__ b2,
         const float* __restrict__ W3, const float* __restrict__ b3,
         const float* __restrict__ x,  const float* __restrict__ data_x,
         const float* __restrict__ data_w,
         float* __restrict__ out)
{
    extern __shared__ char sm[];
    char*  A0p  = sm + SM_A0;
    float* DstA = (float*)(sm + SM_DSTA);
    float* DstB = (float*)(sm + SM_DSTB);
    float* sb1  = (float*)(sm + SM_SB1);
    float* sb2  = (float*)(sm + SM_SB2);

    const int tid     = threadIdx.x;
    const int warp    = tid >> 5;
    const int lane    = tid & 31;
    const int team    = warp >> 3;       // 0: cols 0-63, 1: cols 64-127
    const int wm      = warp & 7;        // m-tile
    const int teamtid = tid & 255;
    const int barid   = 1 + team;
    float* DstT = team ? DstB : DstA;

    const uint32_t smw  = (uint32_t)__cvta_generic_to_shared(sm);
    const uint32_t aA0  = smw + SM_A0;
    const uint32_t aB1H = smw + SM_B1H;
    const uint32_t aB1L = smw + SM_B1L;
    const uint32_t aB2H = smw + SM_B2H;
    const uint32_t aB2L = smw + SM_B2L;

    // ---- build weight splits: Wst[n][k] = W[k][n], fp16 hi/lo, swizzled ----
    for (int idx = tid; idx < 16384; idx += THREADS) {
        int k = idx >> 7, n = idx & 127;
        uint32_t off = swz_off(n, 2 * k);
        float v1 = W1[idx];
        float v2 = W2[idx];
        __half h1 = __float2half(v1);
        __half h2 = __float2half(v2);
        *(__half*)(sm + SM_B1H + off) = h1;
        *(__half*)(sm + SM_B1L + off) = __float2half(v1 - __half2float(h1));
        *(__half*)(sm + SM_B2H + off) = h2;
        *(__half*)(sm + SM_B2L + off) = __float2half(v2 - __half2float(h2));
    }
    if (tid < 128) { sb1[tid] = b1[tid]; sb2[tid] = b2[tid]; }
    __syncthreads();

    // ldmatrix lane address components (swizzled layout)
    const uint32_t sx       = (uint32_t)((lane & 7) << 4);
    const uint32_t baseArow = (uint32_t)((16 * wm + (lane & 15)) * 256);
    const uint32_t cb0A     = (uint32_t)((lane >> 4) * 16);
    const uint32_t baseBrow = (uint32_t)((64 * team + ((lane >> 4) << 3) + (lane & 7)) * 256);
    const uint32_t cb0B     = (uint32_t)(((lane >> 3) & 1) * 16);

    const float CW  = (float)(kWC);
    const float CM  = (float)(-kEI * kWC);
    const float b3v = __ldg(&b3[0]);

    for (int tile = blockIdx.x; tile < NTILES; tile += gridDim.x) {
        const int base = tile * PTILE;
        const int npt  = min(PTILE, TOTALP - base);
        const int NP2  = npt * 16;

        // ---- layer 0: build A (fp16) directly from global coords ----
#pragma unroll
        for (int e = 0; e < 4; e++) {
            int idx = tid + e * THREADS;
            if (idx < npt * 64) {
                int pt = idx >> 6, up = idx & 63;
                int u0 = 2 * up;
                int p = base + pt;
                float s;
                if (p < NPTS)                       s = __ldg(&x[p]);
                else if (p < NPTS + NDATA)          s = __ldg(&data_x[p - NPTS]);
                else if (p < NPTS + NDATA + NQUAD)  s = g_tn[p - NPTS - NDATA];
                else                                s = (p == NPTS + NDATA + NQUAD) ? 0.0f : 1.0f;
                float wa = __ldg(&W0[u0]),     ba = __ldg(&b0[u0]);
                float wb = __ldg(&W0[u0 + 1]), bb = __ldg(&b0[u0 + 1]);
                float ya[5], yb[5];
                tanh_jet(fmaf(wa, s, ba), wa, 0.f, 0.f, 0.f,
                         ya[0], ya[1], ya[2], ya[3], ya[4]);
                tanh_jet(fmaf(wb, s, bb), wb, 0.f, 0.f, 0.f,
                         yb[0], yb[1], yb[2], yb[3], yb[4]);
                int r0 = 5 * pt;
#pragma unroll
                for (int c = 0; c < 5; c++)
                    store_pair_h(A0p, r0 + c, u0, ya[c], yb[c]);
            }
        }
        __syncthreads();

        // ================= LAYER 1 GEMM =================
        float D[8][4];
#pragma unroll
        for (int nt = 0; nt < 8; nt++) { D[nt][0] = D[nt][1] = D[nt][2] = D[nt][3] = 0.f; }
        warp_gemm(aA0, aB1H, aB1L, baseArow, baseBrow, cb0A, cb0B, sx, D);

        // Block-wide barrier: every warp reads ALL of A in the GEMM above;
        // the epilogue below overwrites A.
        __syncthreads();

        // ---- layer 1 epilogue: 2 chunks per team, named barriers ----
        for (int lc = 0; lc < 2; lc++) {
            stage_frags(DstT, D, wm, lane, lc);
            NBAR(barid);
#pragma unroll
            for (int e = 0; e < 2; e++) {
                int idx = teamtid + e * 256;
                if (idx < NP2) {
                    int pt = idx >> 4, up = idx & 15;
                    int u0 = (2 * team + lc) * 32 + 2 * up;
                    float z0[5], z1[5];
#pragma unroll
                    for (int c = 0; c < 5; c++) {
                        float2 zz = *(float2*)&DstT[(5 * pt + c) * DSTRIDE + 2 * up];
                        z0[c] = zz.x; z1[c] = zz.y;
                    }
                    z0[0] += sb1[u0]; z1[0] += sb1[u0 + 1];
                    float ya[5], yb[5];
                    tanh_jet(z0[0], z0[1], z0[2], z0[3], z0[4], ya[0], ya[1], ya[2], ya[3], ya[4]);
                    tanh_jet(z1[0], z1[1], z1[2], z1[3], z1[4], yb[0], yb[1], yb[2], yb[3], yb[4]);
                    int r0 = 5 * pt;
#pragma unroll
                    for (int c = 0; c < 5; c++)
                        store_pair_h(A0p, r0 + c, u0, ya[c], yb[c]);
                }
            }
            NBAR(barid);
        }
        __syncthreads();   // both teams' A writes visible before layer-2 GEMM

        // ================= LAYER 2 GEMM =================
#pragma unroll
        for (int nt = 0; nt < 8; nt++) { D[nt][0] = D[nt][1] = D[nt][2] = D[nt][3] = 0.f; }
        warp_gemm(aA0, aB2H, aB2L, baseArow, baseBrow, cb0A, cb0B, sx, D);
        // (no A writes below until next tile's layer 0; Dst buffers are
        //  team-private, so no block barrier needed here.)

        // ---- layer 2 epilogue + head partials (teams) ----
        float hp[2][5];
#pragma unroll
        for (int e = 0; e < 2; e++)
#pragma unroll
            for (int c = 0; c < 5; c++) hp[e][c] = 0.0f;

        for (int lc = 0; lc < 2; lc++) {
            stage_frags(DstT, D, wm, lane, lc);
            NBAR(barid);
#pragma unroll
            for (int e = 0; e < 2; e++) {
                int idx = teamtid + e * 256;
                if (idx < NP2) {
                    int pt = idx >> 4, up = idx & 15;
                    int u0 = (2 * team + lc) * 32 + 2 * up;
                    float z0[5], z1[5];
#pragma unroll
                    for (int c = 0; c < 5; c++) {
                        float2 zz = *(float2*)&DstT[(5 * pt + c) * DSTRIDE + 2 * up];
                        z0[c] = zz.x; z1[c] = zz.y;
                    }
                    z0[0] += sb2[u0]; z1[0] += sb2[u0 + 1];
                    float ya[5], yb[5];
                    tanh_jet(z0[0], z0[1], z0[2], z0[3], z0[4], ya[0], ya[1], ya[2], ya[3], ya[4]);
                    tanh_jet(z1[0], z1[1], z1[2], z1[3], z1[4], yb[0], yb[1], yb[2], yb[3], yb[4]);
                    float wa = __ldg(&W3[u0]), wb = __ldg(&W3[u0 + 1]);
#pragma unroll
                    for (int c = 0; c < 5; c++)
                        hp[e][c] = fmaf(wa, ya[c], fmaf(wb, yb[c], hp[e][c]));
                }
            }
            NBAR(barid);
        }

        // ---- head partials -> team buffer (stride 17) ----
#pragma unroll
        for (int e = 0; e < 2; e++) {
            int idx = teamtid + e * 256;
            if (idx < NP2) {
                int pt = idx >> 4, up = idx & 15;
#pragma unroll
                for (int c = 0; c < 5; c++)
                    DstT[(pt * 5 + c) * HSTRIDE + up] = hp[e][c];
            }
        }
        __syncthreads();

        // ---- fixed-order reduce over both teams' partials ----
        if (tid < npt * 5) {
            int pt = tid / 5, c = tid % 5;
            float v = 0.0f;
            const float* sa = DstA + tid * HSTRIDE;
            const float* sb = DstB + tid * HSTRIDE;
#pragma unroll
            for (int up = 0; up < 16; up++) v += sa[up];
#pragma unroll
            for (int up = 0; up < 16; up++) v += sb[up];
            if (c == 0) v += b3v;
            write_point(out, base + pt, c, v, CW, CM);
        }
        // next tile's layer0 writes only A; its post-layer0 __syncthreads
        // orders everything before the GEMM.
    }

    // ======================= fused finalize (last block) =======================
    __threadfence();
    __syncthreads();
    volatile int* is_last = (volatile int*)(sm + SM_SB1);   // sb1 dead after loop
    if (tid == 0) {
        unsigned int v = atomicAdd(&g_done, 1u);
        *is_last = (v == (unsigned)(gridDim.x - 1)) ? 1 : 0;
    }
    __syncthreads();
    if (*is_last) {
        __threadfence();
        double* sd = (double*)(sm);

        double acc = 0.0;
        for (int i = tid; i < NQUAD; i += THREADS) acc += (double)g_fsq[i];
        sd[tid] = acc;
        __syncthreads();
        for (int off = THREADS / 2; off > 0; off >>= 1) {
            if (tid < off) sd[tid] += sd[tid + off];
            __syncthreads();
        }
        double S_fsq = sd[0];
        __syncthreads();

        const float wcf = (float)kWC;
        double accd = 0.0;
        for (int i = tid; i < NDATA; i += THREADS) {
            float r = g_pred[i] - data_w[i] / wcf;
            accd += (double)(r * r);
        }
        sd[tid] = accd;
        __syncthreads();
        for (int off = THREADS / 2; off > 0; off >>= 1) {
            if (tid < off) sd[tid] += sd[tid + off];
            __syncthreads();
        }
        double S_data = sd[0];

        if (tid == 0) {
            float quad   = g_wsum * (float)S_fsq;
            float inter  = (float)(0.5 * kEI * (kWC * kWC) * 0.5) * quad;
            float wL     = g_bdry[5];
            float exter  = (float)(5.0 * kWC) * wL;
            float res_pel = inter - exter;

            float w0v = g_bdry[0], dw0 = g_bdry[1];
            float res_dir = (w0v * w0v + dw0 * dw0) * 0.5f;

            float ddwL = g_bdry[7], dddwL = g_bdry[8];
            float Fb   = (float)(-kEI * kWC) * dddwL;
            float tnn  = Fb / 5.0f - 1.0f;
            float res_neu = (tnn * tnn + ddwL * ddwL) * 0.5f;

            float res_data = (float)(S_data / (double)NDATA);

            out[5 * NPTS] = res_pel + (res_dir + res_neu) * 0.5f + res_data;
            g_done = 0;   // reset for next graph replay
        }
    }
}

// ============================================================================
// kernel_launch
// ============================================================================
extern "C" void kernel_launch(void* const* d_in, const int* in_sizes, int n_in,
                              void* d_out, int out_size)
{
    (void)n_in; (void)out_size;
    const float *W0, *b0, *W1, *b1, *W2, *b2, *W3, *b3, *x, *dxp, *dwp;
    if (in_sizes[0] == NPTS) {
        x   = (const float*)d_in[0];
        dxp = (const float*)d_in[1];
        dwp = (const float*)d_in[2];
        W0  = (const float*)d_in[3];  b0 = (const float*)d_in[4];
        W1  = (const float*)d_in[5];  b1 = (const float*)d_in[6];
        W2  = (const float*)d_in[7];  b2 = (const float*)d_in[8];
        W3  = (const float*)d_in[9];  b3 = (const float*)d_in[10];
    } else {
        W0  = (const float*)d_in[0];  b0 = (const float*)d_in[1];
        W1  = (const float*)d_in[2];  b1 = (const float*)d_in[3];
        W2  = (const float*)d_in[4];  b2 = (const float*)d_in[5];
        W3  = (const float*)d_in[6];  b3 = (const float*)d_in[7];
        x   = (const float*)d_in[8];
        dxp = (const float*)d_in[9];
        dwp = (const float*)d_in[10];
    }

    cudaMemcpyToSymbolAsync(g_tn,   g_gl.tn,    sizeof(float) * NQUAD, 0,
                            cudaMemcpyHostToDevice, 0);
    cudaMemcpyToSymbolAsync(g_wsum, &g_gl.wsum, sizeof(float), 0,
                            cudaMemcpyHostToDevice, 0);

    int sms = 148;
    cudaDeviceGetAttribute(&sms, cudaDevAttrMultiProcessorCount, 0);

    cudaFuncSetAttribute(pinn_mma, cudaFuncAttributeMaxDynamicSharedMemorySize,
                         SMEM_BYTES);

    pinn_mma<<<sms, THREADS, SMEM_BYTES>>>(W0, b0, W1, b1, W2, b2, W3, b3,
                                           x, dxp, dwp, (float*)d_out);
}